// round 3
// baseline (speedup 1.0000x reference)
#include <cuda_runtime.h>

#define BATCH 8
#define CH    512
#define PIX   4096            // 64*64
#define CP    (CH*PIX)        // 2,097,152
#define TOT   (BATCH*CP)      // 16,777,216

// Scratch (device globals: allocation-free per harness rules)
__device__ float  g_f[2][TOT];     // conv outputs f_opt / f_sar
__device__ float  g_S[2][TOT];     // Gram matrices S_opt / S_sar
__device__ float4 g_red[BATCH*PIX]; // per-(b,pixel): (m1, z1, m2, z2)

// ---------------------------------------------------------------------------
// Kernel A: 1x1 conv as SGEMM.  F[b][o][p] = sum_c W[o][c] * X[b][c][p]
// M=512 (o), N=4096 (p), K=512 (c); 16 GEMMs (8 batches x 2 branches).
// 128x128 block tile, BK=8, 8x8 per thread, 256 threads, double-buffered smem.
// ---------------------------------------------------------------------------
__global__ __launch_bounds__(256, 2)
void conv_gemm(const float* __restrict__ opt, const float* __restrict__ sar,
               const float* __restrict__ Wopt, const float* __restrict__ Wsar)
{
    const int branch = blockIdx.z >> 3;
    const int batch  = blockIdx.z & 7;
    const float* __restrict__ Wm = branch ? Wsar : Wopt;
    const float* __restrict__ X  = (branch ? sar : opt) + (size_t)batch * CP;
    float* __restrict__ F = g_f[branch] + (size_t)batch * CP;

    __shared__ float As[2][8][128];   // [k][m]  (transposed on store)
    __shared__ float Bs[2][8][128];   // [k][n]

    const int t      = threadIdx.x;
    const int m_base = blockIdx.y * 128;
    const int n_base = blockIdx.x * 128;

    // loader coordinates
    const int arow = t >> 1;           // 0..127  (m within tile)
    const int acol = (t & 1) * 4;      // 0 or 4  (k within tile)
    const int brow = t >> 5;           // 0..7    (k within tile)
    const int bcol = (t & 31) * 4;     // 0..124  (n within tile)

    const float* Aptr = Wm + (size_t)(m_base + arow) * CH + acol;
    const float* Bptr = X  + (size_t)brow * PIX + n_base + bcol;

    // compute coordinates
    const int m0 = (t >> 4) * 8;
    const int n0 = (t & 15) * 8;

    float acc[8][8];
    #pragma unroll
    for (int i = 0; i < 8; i++)
        #pragma unroll
        for (int j = 0; j < 8; j++) acc[i][j] = 0.f;

    // preload k-tile 0
    {
        float4 a = *(const float4*)(Aptr);
        float4 b = *(const float4*)(Bptr);
        As[0][acol+0][arow] = a.x;
        As[0][acol+1][arow] = a.y;
        As[0][acol+2][arow] = a.z;
        As[0][acol+3][arow] = a.w;
        *(float4*)&Bs[0][brow][bcol] = b;
    }
    __syncthreads();

    for (int kt = 0; kt < 64; ++kt) {
        const int buf = kt & 1;
        float4 an, bn;
        if (kt < 63) {
            an = *(const float4*)(Aptr + (kt + 1) * 8);
            bn = *(const float4*)(Bptr + (size_t)(kt + 1) * 8 * PIX);
        }
        #pragma unroll
        for (int k = 0; k < 8; ++k) {
            float4 a0 = *(const float4*)&As[buf][k][m0];
            float4 a1 = *(const float4*)&As[buf][k][m0 + 4];
            float4 b0 = *(const float4*)&Bs[buf][k][n0];
            float4 b1 = *(const float4*)&Bs[buf][k][n0 + 4];
            float ra[8] = {a0.x, a0.y, a0.z, a0.w, a1.x, a1.y, a1.z, a1.w};
            float rb[8] = {b0.x, b0.y, b0.z, b0.w, b1.x, b1.y, b1.z, b1.w};
            #pragma unroll
            for (int i = 0; i < 8; i++)
                #pragma unroll
                for (int j = 0; j < 8; j++)
                    acc[i][j] = fmaf(ra[i], rb[j], acc[i][j]);
        }
        if (kt < 63) {
            const int nb = buf ^ 1;
            As[nb][acol+0][arow] = an.x;
            As[nb][acol+1][arow] = an.y;
            As[nb][acol+2][arow] = an.z;
            As[nb][acol+3][arow] = an.w;
            *(float4*)&Bs[nb][brow][bcol] = bn;
            __syncthreads();
        }
    }

    #pragma unroll
    for (int i = 0; i < 8; i++) {
        float* o = F + (size_t)(m_base + m0 + i) * PIX + n_base + n0;
        *(float4*)(o)     = make_float4(acc[i][0], acc[i][1], acc[i][2], acc[i][3]);
        *(float4*)(o + 4) = make_float4(acc[i][4], acc[i][5], acc[i][6], acc[i][7]);
    }
}

// ---------------------------------------------------------------------------
// Kernel B: per-(b,c) Gram matrix S = f^T f (64x64x64), both branches per CTA.
// 128 threads: threads [0,64) -> branch 0, [64,128) -> branch 1.
// Each thread computes an 8x8 output tile.
// ---------------------------------------------------------------------------
__global__ __launch_bounds__(128)
void attn_gemm()
{
    const int bc = blockIdx.x;                   // 0..4095 = b*512+c
    __shared__ float sh[2][64][64];

    const int t = threadIdx.x;

    // cooperative load: 2 * 4096 floats = 2048 float4 / 128 threads = 16 each
    {
        const float4* g0 = (const float4*)(g_f[0] + (size_t)bc * PIX);
        const float4* g1 = (const float4*)(g_f[1] + (size_t)bc * PIX);
        float4* s0 = (float4*)&sh[0][0][0];
        float4* s1 = (float4*)&sh[1][0][0];
        #pragma unroll
        for (int i = 0; i < 8; i++) {
            s0[t + 128 * i] = g0[t + 128 * i];
            s1[t + 128 * i] = g1[t + 128 * i];
        }
    }
    __syncthreads();

    const int branch = t >> 6;
    const int tt = t & 63;
    const int i0 = (tt >> 3) * 8;
    const int j0 = (tt & 7) * 8;

    float acc[8][8];
    #pragma unroll
    for (int i = 0; i < 8; i++)
        #pragma unroll
        for (int j = 0; j < 8; j++) acc[i][j] = 0.f;

    for (int h = 0; h < 64; ++h) {
        float4 a0 = *(const float4*)&sh[branch][h][i0];
        float4 a1 = *(const float4*)&sh[branch][h][i0 + 4];
        float4 b0 = *(const float4*)&sh[branch][h][j0];
        float4 b1 = *(const float4*)&sh[branch][h][j0 + 4];
        float ra[8] = {a0.x, a0.y, a0.z, a0.w, a1.x, a1.y, a1.z, a1.w};
        float rb[8] = {b0.x, b0.y, b0.z, b0.w, b1.x, b1.y, b1.z, b1.w};
        #pragma unroll
        for (int i = 0; i < 8; i++)
            #pragma unroll
            for (int j = 0; j < 8; j++)
                acc[i][j] = fmaf(ra[i], rb[j], acc[i][j]);
    }

    float* S = g_S[branch] + (size_t)bc * PIX;
    #pragma unroll
    for (int i = 0; i < 8; i++) {
        float* o = S + (i0 + i) * 64 + j0;
        *(float4*)(o)     = make_float4(acc[i][0], acc[i][1], acc[i][2], acc[i][3]);
        *(float4*)(o + 4) = make_float4(acc[i][4], acc[i][5], acc[i][6], acc[i][7]);
    }
}

// ---------------------------------------------------------------------------
// Kernel C: online softmax statistics over channel dim for both branches.
// One thread per (b, pixel); coalesced strided reads over c.
// ---------------------------------------------------------------------------
__global__ __launch_bounds__(256)
void softmax_stats()
{
    const int p = blockIdx.x * 256 + threadIdx.x;   // 0..4095
    const int b = blockIdx.y;
    const float* __restrict__ s1 = g_S[0] + (size_t)b * CP + p;
    const float* __restrict__ s2 = g_S[1] + (size_t)b * CP + p;

    float m1 = -3.4e38f, z1 = 0.f;
    float m2 = -3.4e38f, z2 = 0.f;
    #pragma unroll 8
    for (int c = 0; c < CH; ++c) {
        float v1 = s1[c * PIX];
        float v2 = s2[c * PIX];
        float nm1 = fmaxf(m1, v1);
        z1 = z1 * __expf(m1 - nm1) + __expf(v1 - nm1);
        m1 = nm1;
        float nm2 = fmaxf(m2, v2);
        z2 = z2 * __expf(m2 - nm2) + __expf(v2 - nm2);
        m2 = nm2;
    }
    g_red[b * PIX + p] = make_float4(m1, z1, m2, z2);
}

// ---------------------------------------------------------------------------
// Kernel D: Att = f_opt * f_sar * (softmax1 * softmax2)^2
//         = f1*f2 * exp(2*((s1-m1)+(s2-m2))) / (z1*z2)^2
// ---------------------------------------------------------------------------
__global__ __launch_bounds__(256)
void finalize(float* __restrict__ out)
{
    const int e = blockIdx.x * 256 + threadIdx.x;
    const int b = e >> 21;          // / (CH*PIX)
    const int p = e & (PIX - 1);
    float4 r = g_red[(b << 12) + p];
    float s1 = g_S[0][e];
    float s2 = g_S[1][e];
    float f1 = g_f[0][e];
    float f2 = g_f[1][e];
    float rz = 1.0f / (r.y * r.w);
    float ex = __expf(2.0f * ((s1 - r.x) + (s2 - r.z)));
    out[e] = (f1 * f2) * (ex * rz * rz);
}

// ---------------------------------------------------------------------------
extern "C" void kernel_launch(void* const* d_in, const int* in_sizes, int n_in,
                              void* d_out, int out_size)
{
    const float* opt  = (const float*)d_in[0];
    const float* sar  = (const float*)d_in[1];
    const float* Wopt = (const float*)d_in[2];
    const float* Wsar = (const float*)d_in[3];
    float* out = (float*)d_out;

    conv_gemm<<<dim3(32, 4, 16), 256>>>(opt, sar, Wopt, Wsar);
    attn_gemm<<<dim3(4096, 1, 1), 128>>>();
    softmax_stats<<<dim3(16, 8), 256>>>();
    finalize<<<TOT / 256, 256>>>(out);
}